// round 2
// baseline (speedup 1.0000x reference)
#include <cuda_runtime.h>

#define DD 32
#define TILE_E 128

// Rearranged edge weights: W2[(d*32+k)*32 + h] = edge_W[(d*32+h)*32 + k]
__device__ float g_W2[1024 * 32];

__global__ void prep_W2_kernel(const float* __restrict__ edge_W) {
    int idx = blockIdx.x * blockDim.x + threadIdx.x;  // 0..32767
    if (idx < 1024 * 32) {
        int kg = idx >> 5;   // combined (d,k) index
        int h  = idx & 31;
        int d  = kg >> 5;
        int k  = kg & 31;
        g_W2[idx] = edge_W[(d * 32 + h) * 32 + k];
    }
}

// out[n,:] = x[n,:] @ node_W.T   (also initializes the poisoned output buffer)
__global__ void node_kernel(const float* __restrict__ x, const float* __restrict__ nW,
                            float* __restrict__ out, int N) {
    __shared__ float sW[32 * 32];
    int t = threadIdx.x;
    for (int i = t; i < 1024; i += blockDim.x) sW[i] = nW[i];
    __syncthreads();
    int n = blockIdx.x * blockDim.x + t;
    if (n >= N) return;
    float xr[32];
    const float4* xv = (const float4*)(x + (size_t)n * 32);
#pragma unroll
    for (int i = 0; i < 8; ++i) {
        float4 v = xv[i];
        xr[i * 4 + 0] = v.x; xr[i * 4 + 1] = v.y;
        xr[i * 4 + 2] = v.z; xr[i * 4 + 3] = v.w;
    }
    float4* ov = (float4*)(out + (size_t)n * 32);
#pragma unroll
    for (int hq = 0; hq < 8; ++hq) {
        float a0 = 0.f, a1 = 0.f, a2 = 0.f, a3 = 0.f;
#pragma unroll
        for (int d = 0; d < 32; ++d) {
            float xd = xr[d];
            a0 += xd * sW[(hq * 4 + 0) * 32 + d];
            a1 += xd * sW[(hq * 4 + 1) * 32 + d];
            a2 += xd * sW[(hq * 4 + 2) * 32 + d];
            a3 += xd * sW[(hq * 4 + 3) * 32 + d];
        }
        ov[hq] = make_float4(a0, a1, a2, a3);
    }
}

__device__ __forceinline__ void ffma2(unsigned long long& d,
                                      unsigned long long a,
                                      unsigned long long b) {
    asm("fma.rn.f32x2 %0, %1, %2, %3;" : "=l"(d) : "l"(a), "l"(b), "l"(d));
}
__device__ __forceinline__ unsigned long long pack_dup(float x) {
    unsigned long long r;
    unsigned int u = __float_as_uint(x);
    asm("mov.b64 %0, {%1, %2};" : "=l"(r) : "r"(u), "r"(u));
    return r;
}

// Fused: msgs = (x_j outer ea) @ W2, scatter-added into out via atomics.
// CTA: 128 edges x 32 h. 256 threads, each 4 edges x 4 h outputs.
__global__ void __launch_bounds__(256)
edge_kernel(const float* __restrict__ x, const float* __restrict__ ea,
            const int* __restrict__ src_idx, const int* __restrict__ dst_idx,
            float* __restrict__ out, int E) {
    extern __shared__ float smem[];
    float* s_x  = smem;                       // [128][33]
    float* s_ea = smem + 128 * 33;            // [128][33]
    float* s_B  = s_ea + 128 * 33;            // [2][128][32]
    int*   s_dst = (int*)(s_B + 2 * 128 * 32);// [128]

    const int t  = threadIdx.x;
    const int e0 = blockIdx.x * TILE_E;

    if (t < TILE_E) {
        int e = e0 + t;
        s_dst[t] = (e < E) ? dst_idx[e] : 0;
    }

    // Gather x_j and edge_attr tiles (vector LDG, scalar conflict-free STS)
    {
        int c4 = (t & 7) * 4;
        for (int rr = (t >> 3); rr < TILE_E; rr += 32) {
            int e = e0 + rr;
            float4 xv = make_float4(0.f, 0.f, 0.f, 0.f);
            float4 av = make_float4(0.f, 0.f, 0.f, 0.f);
            if (e < E) {
                int s = src_idx[e];
                xv = *(const float4*)(x + (size_t)s * 32 + c4);
                av = *(const float4*)(ea + (size_t)e * 32 + c4);
            }
            float* px = s_x + rr * 33 + c4;
            px[0] = xv.x; px[1] = xv.y; px[2] = xv.z; px[3] = xv.w;
            float* pa = s_ea + rr * 33 + c4;
            pa[0] = av.x; pa[1] = av.y; pa[2] = av.z; pa[3] = av.w;
        }
    }

    const int h0 = (t & 7) * 4;   // 4 consecutive output columns
    const int eL = (t >> 3) * 4;  // 4 consecutive edges within tile

    unsigned long long acc[4][2];
#pragma unroll
    for (int i = 0; i < 4; ++i) { acc[i][0] = 0ull; acc[i][1] = 0ull; }

    const float4* W2v = (const float4*)g_W2;  // 8 chunks x 1024 float4

    // Prefetch chunk 0 of W2 into smem buffer 0
    float4 pb0 = W2v[t], pb1 = W2v[t + 256], pb2 = W2v[t + 512], pb3 = W2v[t + 768];
    {
        float4* dsts = (float4*)s_B;
        dsts[t] = pb0; dsts[t + 256] = pb1; dsts[t + 512] = pb2; dsts[t + 768] = pb3;
    }
    __syncthreads();

    const float* pe0 = s_ea + (eL + 0) * 33;
    const float* pe1 = s_ea + (eL + 1) * 33;
    const float* pe2 = s_ea + (eL + 2) * 33;
    const float* pe3 = s_ea + (eL + 3) * 33;

#pragma unroll 1
    for (int c = 0; c < 8; ++c) {
        if (c < 7) {  // prefetch next chunk into registers
            const float4* p = W2v + (c + 1) * 1024;
            pb0 = p[t]; pb1 = p[t + 256]; pb2 = p[t + 512]; pb3 = p[t + 768];
        }
        const float* B = s_B + (c & 1) * (128 * 32);

#pragma unroll
        for (int kd = 0; kd < 4; ++kd) {
            const int dg = c * 4 + kd;  // global d index of this 32-k phase
            const float xr0 = s_x[(eL + 0) * 33 + dg];
            const float xr1 = s_x[(eL + 1) * 33 + dg];
            const float xr2 = s_x[(eL + 2) * 33 + dg];
            const float xr3 = s_x[(eL + 3) * 33 + dg];

            for (int kk8 = 0; kk8 < 32; kk8 += 8) {
#pragma unroll
                for (int u = 0; u < 8; ++u) {
                    const int kl = kk8 + u;         // edge_attr index (0..31)
                    const int kB = kd * 32 + kl;    // row within W2 chunk (0..127)
                    const ulonglong2 bv = *(const ulonglong2*)(B + kB * 32 + h0);
                    unsigned long long a;
                    a = pack_dup(xr0 * pe0[kl]); ffma2(acc[0][0], a, bv.x); ffma2(acc[0][1], a, bv.y);
                    a = pack_dup(xr1 * pe1[kl]); ffma2(acc[1][0], a, bv.x); ffma2(acc[1][1], a, bv.y);
                    a = pack_dup(xr2 * pe2[kl]); ffma2(acc[2][0], a, bv.x); ffma2(acc[2][1], a, bv.y);
                    a = pack_dup(xr3 * pe3[kl]); ffma2(acc[3][0], a, bv.x); ffma2(acc[3][1], a, bv.y);
                }
            }
        }
        __syncthreads();
        if (c < 7) {
            float4* dsts = (float4*)(s_B + ((c + 1) & 1) * (128 * 32));
            dsts[t] = pb0; dsts[t + 256] = pb1; dsts[t + 512] = pb2; dsts[t + 768] = pb3;
            __syncthreads();
        }
    }

    // Scatter-add messages
#pragma unroll
    for (int i = 0; i < 4; ++i) {
        int e = e0 + eL + i;
        if (e < E) {
            float* op = out + (size_t)s_dst[eL + i] * 32 + h0;
            unsigned long long a0 = acc[i][0], a1 = acc[i][1];
            atomicAdd(op + 0, __uint_as_float((unsigned int)(a0 & 0xffffffffu)));
            atomicAdd(op + 1, __uint_as_float((unsigned int)(a0 >> 32)));
            atomicAdd(op + 2, __uint_as_float((unsigned int)(a1 & 0xffffffffu)));
            atomicAdd(op + 3, __uint_as_float((unsigned int)(a1 >> 32)));
        }
    }
}

extern "C" void kernel_launch(void* const* d_in, const int* in_sizes, int n_in,
                              void* d_out, int out_size) {
    const float* x      = (const float*)d_in[0];  // [N,32]
    const float* ea     = (const float*)d_in[1];  // [E,32]
    const float* edge_W = (const float*)d_in[2];  // [1024,32]
    const float* node_W = (const float*)d_in[3];  // [32,32]
    const int*   ei     = (const int*)d_in[4];    // [2,E]
    float* out = (float*)d_out;

    const int N = in_sizes[0] / DD;
    const int E = in_sizes[4] / 2;
    const int* src = ei;
    const int* dst = ei + E;

    static bool attr_set = false;
    const int smem_bytes = (128 * 33 * 2 + 2 * 128 * 32) * 4 + 128 * 4;
    if (!attr_set) {
        cudaFuncSetAttribute(edge_kernel,
                             cudaFuncAttributeMaxDynamicSharedMemorySize, smem_bytes);
        attr_set = true;
    }

    prep_W2_kernel<<<(1024 * 32 + 255) / 256, 256>>>(edge_W);
    node_kernel<<<(N + 127) / 128, 128>>>(x, node_W, out, N);
    edge_kernel<<<(E + TILE_E - 1) / TILE_E, 256, smem_bytes>>>(x, ea, src, dst, out, E);
}

// round 4
// speedup vs baseline: 6.5067x; 6.5067x over previous
#include <cuda_runtime.h>
#include <cstdint>

#define DD 32
#define TILE_E 128
#define NTH 256

// ---------------- smem layout (bytes) ----------------
#define SB_OFF 0                     // 8192 uint2 B-fragments = 65536
#define SX_OFF 65536                 // x half2-dup [128][36] u32 = 18432
#define SC_OFF (65536 + 18432)       // msgs staging [128][36] f32 = 18432
#define SMEM_BYTES (65536 + 18432 + 18432)   // 102400

// Pre-built per-lane B fragments: [ks(64)][nt(4)][lane(32)] -> {b0,b1}
__device__ uint2 g_Bfrag[64 * 4 * 32];

__device__ __forceinline__ uint32_t h2pack(float lo, float hi) {
    uint32_t r;
    asm("cvt.rn.f16x2.f32 %0, %1, %2;" : "=r"(r) : "f"(hi), "f"(lo));
    return r;
}
__device__ __forceinline__ uint32_t h2dup(float f) {
    uint32_t r;
    asm("{\n\t.reg .b16 h;\n\tcvt.rn.f16.f32 h, %1;\n\tmov.b32 %0, {h, h};\n\t}"
        : "=r"(r) : "f"(f));
    return r;
}
__device__ __forceinline__ uint32_t hmul2(uint32_t a, uint32_t b) {
    uint32_t r;
    asm("mul.rn.f16x2 %0, %1, %2;" : "=r"(r) : "r"(a), "r"(b));
    return r;
}
__device__ __forceinline__ void mma16816(float c[4], uint32_t a0, uint32_t a1,
                                         uint32_t a2, uint32_t a3,
                                         uint32_t b0, uint32_t b1) {
    asm volatile(
        "mma.sync.aligned.m16n8k16.row.col.f32.f16.f16.f32 "
        "{%0,%1,%2,%3}, {%4,%5,%6,%7}, {%8,%9}, {%0,%1,%2,%3};"
        : "+f"(c[0]), "+f"(c[1]), "+f"(c[2]), "+f"(c[3])
        : "r"(a0), "r"(a1), "r"(a2), "r"(a3), "r"(b0), "r"(b1));
}
__device__ __forceinline__ void red_add_v4(float* p, float a, float b, float c, float d) {
    asm volatile("red.global.add.v4.f32 [%0], {%1, %2, %3, %4};"
                 :: "l"(p), "f"(a), "f"(b), "f"(c), "f"(d) : "memory");
}

// Build fp16 B fragments. Logical B[kg][h] = edge_W[((kg>>5)*32 + h)*32 + (kg&31)]
__global__ void prep_Bfrag(const float* __restrict__ eW) {
    int idx = blockIdx.x * blockDim.x + threadIdx.x;   // 0..8191
    if (idx >= 64 * 4 * 32) return;
    int lane = idx & 31, nt = (idx >> 5) & 3, ks = idx >> 7;
    int g = lane >> 2, tig = lane & 3;
    int col = nt * 8 + g;
    int kg0 = ks * 16;
    auto B = [&](int kg) { return eW[((kg >> 5) * 32 + col) * 32 + (kg & 31)]; };
    uint2 r;
    r.x = h2pack(B(kg0 + 2 * tig),     B(kg0 + 2 * tig + 1));
    r.y = h2pack(B(kg0 + 2 * tig + 8), B(kg0 + 2 * tig + 9));
    g_Bfrag[idx] = r;
}

// out[n,:] = x[n,:] @ node_W.T  (also initializes the poisoned output buffer)
__global__ void node_kernel(const float* __restrict__ x, const float* __restrict__ nW,
                            float* __restrict__ out, int N) {
    __shared__ float sW[32 * 32];
    int t = threadIdx.x;
    for (int i = t; i < 1024; i += blockDim.x) sW[i] = nW[i];
    __syncthreads();
    int n = blockIdx.x * blockDim.x + t;
    if (n >= N) return;
    float xr[32];
    const float4* xv = (const float4*)(x + (size_t)n * 32);
#pragma unroll
    for (int i = 0; i < 8; ++i) {
        float4 v = xv[i];
        xr[i * 4 + 0] = v.x; xr[i * 4 + 1] = v.y;
        xr[i * 4 + 2] = v.z; xr[i * 4 + 3] = v.w;
    }
    float4* ov = (float4*)(out + (size_t)n * 32);
#pragma unroll
    for (int hq = 0; hq < 8; ++hq) {
        float a0 = 0.f, a1 = 0.f, a2 = 0.f, a3 = 0.f;
#pragma unroll
        for (int d = 0; d < 32; ++d) {
            float xd = xr[d];
            a0 += xd * sW[(hq * 4 + 0) * 32 + d];
            a1 += xd * sW[(hq * 4 + 1) * 32 + d];
            a2 += xd * sW[(hq * 4 + 2) * 32 + d];
            a3 += xd * sW[(hq * 4 + 3) * 32 + d];
        }
        ov[hq] = make_float4(a0, a1, a2, a3);
    }
}

// Persistent fused edge kernel: msgs = (x_j outer ea) @ W2 via mma.sync fp16,
// scatter-added to out with vector reductions.
__global__ void __launch_bounds__(NTH, 2)
edge_kernel(const float* __restrict__ x, const float* __restrict__ ea,
            const int* __restrict__ src_idx, const int* __restrict__ dst_idx,
            float* __restrict__ out, int E, int ntiles) {
    extern __shared__ char smem[];
    uint32_t* sX = (uint32_t*)(smem + SX_OFF);   // [128][36] half2-dup of x rows
    float*    sC = (float*)(smem + SC_OFF);      // [128][36] staged messages
    uint32_t* sB = (uint32_t*)(smem + SB_OFF);   // B fragments (uint2 granules)

    const int t = threadIdx.x;
    const int lane = t & 31, w = t >> 5;
    const int g = lane >> 2, tig = lane & 3;
    const int rloc0 = w * 16 + g, rloc1 = rloc0 + 8;

    // Load B fragments once per CTA (64 KB)
    {
        const uint4* gb = (const uint4*)g_Bfrag;
        uint4* sb4 = (uint4*)(smem + SB_OFF);
#pragma unroll
        for (int i = 0; i < 16; ++i) sb4[t + i * NTH] = gb[t + i * NTH];
    }

    for (int tile = blockIdx.x; tile < ntiles; tile += gridDim.x) {
        const int e0 = tile * TILE_E;

        // ---- gather x_j rows into smem as half2-dups ----
        {
            int row = t >> 1, part = t & 1;
            int ec = min(e0 + row, E - 1);
            int s = src_idx[ec];
            const float4* xp = (const float4*)(x + (size_t)s * 32 + part * 16);
            uint32_t* dp = sX + row * 36 + part * 16;
#pragma unroll
            for (int j = 0; j < 4; ++j) {
                float4 v = xp[j];
                uint4 o;
                o.x = h2dup(v.x); o.y = h2dup(v.y); o.z = h2dup(v.z); o.w = h2dup(v.w);
                *(uint4*)(dp + j * 4) = o;
            }
        }

        // ---- edge_attr pairs into registers (fp16) ----
        uint32_t eg[4], eh[4];
        {
            int ec0 = min(e0 + rloc0, E - 1);
            int ec1 = min(e0 + rloc1, E - 1);
            const float* p0 = ea + (size_t)ec0 * 32;
            const float* p1 = ea + (size_t)ec1 * 32;
#pragma unroll
            for (int m = 0; m < 4; ++m) {
                float2 a = *(const float2*)(p0 + m * 8 + 2 * tig);
                float2 b = *(const float2*)(p1 + m * 8 + 2 * tig);
                eg[m] = h2pack(a.x, a.y);
                eh[m] = h2pack(b.x, b.y);
            }
        }

        float c[4][4];
#pragma unroll
        for (int nt = 0; nt < 4; ++nt)
#pragma unroll
            for (int q = 0; q < 4; ++q) c[nt][q] = 0.f;

        __syncthreads();  // sX ready; prev tile's sC reads complete

        // ---- main loop: 32 d x 2 k-halves x 4 n-tiles of m16n8k16 ----
#pragma unroll 4
        for (int d = 0; d < 32; ++d) {
            uint32_t xg = sX[rloc0 * 36 + d];
            uint32_t xh = sX[rloc1 * 36 + d];
#pragma unroll
            for (int half = 0; half < 2; ++half) {
                uint32_t a0 = hmul2(xg, eg[half * 2 + 0]);
                uint32_t a1 = hmul2(xh, eh[half * 2 + 0]);
                uint32_t a2 = hmul2(xg, eg[half * 2 + 1]);
                uint32_t a3 = hmul2(xh, eh[half * 2 + 1]);
                int ks = 2 * d + half;
#pragma unroll
                for (int nt = 0; nt < 4; ++nt) {
                    uint2 b = *(const uint2*)(sB + ((ks * 4 + nt) * 32 + lane) * 2);
                    mma16816(c[nt], a0, a1, a2, a3, b.x, b.y);
                }
            }
        }

        // ---- stage C to smem ----
#pragma unroll
        for (int nt = 0; nt < 4; ++nt) {
            *(float2*)(sC + rloc0 * 36 + nt * 8 + 2 * tig) = make_float2(c[nt][0], c[nt][1]);
            *(float2*)(sC + rloc1 * 36 + nt * 8 + 2 * tig) = make_float2(c[nt][2], c[nt][3]);
        }
        __syncthreads();

        // ---- scatter-add: one thread per edge row, vector reductions ----
        if (t < TILE_E) {
            int e = e0 + t;
            if (e < E) {
                int dv = dst_idx[e];
                float* op = out + (size_t)dv * 32;
                const float* cr = sC + t * 36;
#pragma unroll
                for (int j = 0; j < 8; ++j) {
                    float4 v = *(const float4*)(cr + j * 4);
                    red_add_v4(op + j * 4, v.x, v.y, v.z, v.w);
                }
            }
        }
    }
}

extern "C" void kernel_launch(void* const* d_in, const int* in_sizes, int n_in,
                              void* d_out, int out_size) {
    const float* x      = (const float*)d_in[0];  // [N,32]
    const float* ea     = (const float*)d_in[1];  // [E,32]
    const float* edge_W = (const float*)d_in[2];  // [1024,32]
    const float* node_W = (const float*)d_in[3];  // [32,32]
    const int*   ei     = (const int*)d_in[4];    // [2,E]
    float* out = (float*)d_out;

    const int N = in_sizes[0] / DD;
    const int E = in_sizes[4] / 2;
    const int ntiles = (E + TILE_E - 1) / TILE_E;
    const int* src = ei;
    const int* dst = ei + E;

    static bool attr_set = false;
    if (!attr_set) {
        cudaFuncSetAttribute(edge_kernel,
                             cudaFuncAttributeMaxDynamicSharedMemorySize, SMEM_BYTES);
        attr_set = true;
    }

    prep_Bfrag<<<32, 256>>>(edge_W);
    node_kernel<<<(N + 127) / 128, 128>>>(x, node_W, out, N);

    int grid = ntiles < 296 ? ntiles : 296;
    edge_kernel<<<grid, NTH, SMEM_BYTES>>>(x, ea, src, dst, out, E, ntiles);
}